// round 1
// baseline (speedup 1.0000x reference)
#include <cuda_runtime.h>
#include <cuda_bf16.h>
#include <cstdint>

// Problem shape (fixed): field (2,2048,1024) f32, measurement_ops (32000,1024) f32
// Output: tokens (2,2048) then probs (2,2048,32000), both as float32, concatenated.
#define BB 2
#define SS 2048
#define DD 1024
#define VV 32000
#define NROWS (BB * SS)            // 4096
#define THRESHOLD 0.91f

// Scratch (no cudaMalloc allowed)
__device__ float g_rowsum[NROWS];
__device__ float g_coh[NROWS];

// ---------------------------------------------------------------------------
// zero scratch (must run every launch: graph is replayed)
// ---------------------------------------------------------------------------
__global__ void zero_kernel() {
    int i = blockIdx.x * blockDim.x + threadIdx.x;
    if (i < NROWS) g_rowsum[i] = 0.0f;
}

// ---------------------------------------------------------------------------
// coherence: per (b,s), 5x5 windowed Gram -> lambda_max / trace
// ---------------------------------------------------------------------------
__global__ void __launch_bounds__(128) coherence_kernel(const float* __restrict__ field) {
    int row = blockIdx.x;                 // b*S + s
    int b = row >> 11;
    int s = row & (SS - 1);
    int tid = threadIdx.x;
    const float* base = field + (size_t)b * SS * DD;

    int   idxc[5];
    float valm[5];
    float cnt = 0.0f;
#pragma unroll
    for (int w = 0; w < 5; ++w) {
        int t = s - 2 + w;
        bool v = (t >= 0) && (t < SS);
        valm[w] = v ? 1.0f : 0.0f;
        cnt += valm[w];
        idxc[w] = t < 0 ? 0 : (t > SS - 1 ? SS - 1 : t);
    }
    float rcnt = 1.0f / cnt;

    float g[15];
#pragma unroll
    for (int k = 0; k < 15; ++k) g[k] = 0.0f;

    for (int d = tid; d < DD; d += 128) {
        float f[5];
#pragma unroll
        for (int w = 0; w < 5; ++w) f[w] = base[(size_t)idxc[w] * DD + d];
        float mean = 0.0f;
#pragma unroll
        for (int w = 0; w < 5; ++w) mean += f[w] * valm[w];
        mean *= rcnt;
        float c[5];
#pragma unroll
        for (int w = 0; w < 5; ++w) c[w] = (f[w] - mean) * valm[w];
        int k = 0;
#pragma unroll
        for (int w = 0; w < 5; ++w)
#pragma unroll
            for (int v = w; v < 5; ++v) g[k++] += c[w] * c[v];
    }

    // warp reduce each of 15 sums
#pragma unroll
    for (int k = 0; k < 15; ++k) {
#pragma unroll
        for (int off = 16; off > 0; off >>= 1)
            g[k] += __shfl_xor_sync(0xffffffffu, g[k], off);
    }
    __shared__ float sg[4][15];
    int wid = tid >> 5, ln = tid & 31;
    if (ln == 0) {
#pragma unroll
        for (int k = 0; k < 15; ++k) sg[wid][k] = g[k];
    }
    __syncthreads();

    if (tid == 0) {
        float G[5][5];
        int k = 0;
        for (int w = 0; w < 5; ++w)
            for (int v = w; v < 5; ++v) {
                float val = (sg[0][k] + sg[1][k] + sg[2][k] + sg[3][k]) * rcnt;
                G[w][v] = val;
                G[v][w] = val;
                ++k;
            }
        float tr = 0.0f;
        for (int i = 0; i < 5; ++i) tr += G[i][i];

        // power iteration for lambda_max (PSD matrix; start off the nullspace)
        float vv[5] = {0.8147f, -0.9058f, 0.1270f, 0.9134f, -0.6324f};
        for (int it = 0; it < 60; ++it) {
            float nv[5];
            for (int i = 0; i < 5; ++i) {
                float a = 0.0f;
                for (int j = 0; j < 5; ++j) a += G[i][j] * vv[j];
                nv[i] = a;
            }
            float n2 = 0.0f;
            for (int i = 0; i < 5; ++i) n2 += nv[i] * nv[i];
            float inv = rsqrtf(n2 + 1e-30f);
            for (int i = 0; i < 5; ++i) vv[i] = nv[i] * inv;
        }
        float lam = 0.0f;
        for (int i = 0; i < 5; ++i) {
            float gi = 0.0f;
            for (int j = 0; j < 5; ++j) gi += G[i][j] * vv[j];
            lam += vv[i] * gi;
        }
        g_coh[row] = lam / (tr + 1e-8f);
    }
}

// ---------------------------------------------------------------------------
// GEMM: P[m,n] = (A[m,:] . B[n,:])^2, plus per-row partial sums via atomics.
// A = field (4096 x 1024), B = measurement_ops (32000 x 1024), both K-contig.
// Tiles: BM=128, BN=64, BK=16, 256 threads, 8x4 per thread, double-buffered.
// ---------------------------------------------------------------------------
#define BM 128
#define BN 64
#define BK 16
#define NT (DD / BK)   // 64 K-tiles

__global__ void __launch_bounds__(256) gemm_p_kernel(const float* __restrict__ A,
                                                     const float* __restrict__ B,
                                                     float* __restrict__ P) {
    __shared__ float As[2][BK][BM];
    __shared__ float Bs[2][BK][BN];

    int tid = threadIdx.x;
    int tx = tid & 15;       // 0..15 -> N
    int ty = tid >> 4;       // 0..15 -> M
    int mb = blockIdx.x * BM;   // gridDim.x = 32 (M fastest -> B-tile reuse across block group)
    int nb = blockIdx.y * BN;   // gridDim.y = 500

    // A loader: row = tid>>1 (0..127), cols (tid&1)*8 + {0..3, 4..7}
    int a_row = tid >> 1;
    int a_col = (tid & 1) * 8;
    const float* a_ptr = A + (size_t)(mb + a_row) * DD + a_col;
    // B loader: row = tid>>2 (0..63), col = (tid&3)*4
    int b_row = tid >> 2;
    int b_col = (tid & 3) * 4;
    const float* b_ptr = B + (size_t)(nb + b_row) * DD + b_col;

    // preload tile 0
    {
        float4 a0 = *(const float4*)(a_ptr + 0);
        float4 a1 = *(const float4*)(a_ptr + 4);
        float4 b0 = *(const float4*)(b_ptr + 0);
        As[0][a_col + 0][a_row] = a0.x; As[0][a_col + 1][a_row] = a0.y;
        As[0][a_col + 2][a_row] = a0.z; As[0][a_col + 3][a_row] = a0.w;
        As[0][a_col + 4][a_row] = a1.x; As[0][a_col + 5][a_row] = a1.y;
        As[0][a_col + 6][a_row] = a1.z; As[0][a_col + 7][a_row] = a1.w;
        Bs[0][b_col + 0][b_row] = b0.x; Bs[0][b_col + 1][b_row] = b0.y;
        Bs[0][b_col + 2][b_row] = b0.z; Bs[0][b_col + 3][b_row] = b0.w;
    }
    __syncthreads();

    float acc[8][4];
#pragma unroll
    for (int i = 0; i < 8; ++i)
#pragma unroll
        for (int j = 0; j < 4; ++j) acc[i][j] = 0.0f;

    int buf = 0;
    float4 pa0, pa1, pb0;

#pragma unroll 1
    for (int t = 0; t < NT; ++t) {
        if (t < NT - 1) {
            int k0 = (t + 1) * BK;
            pa0 = *(const float4*)(a_ptr + k0);
            pa1 = *(const float4*)(a_ptr + k0 + 4);
            pb0 = *(const float4*)(b_ptr + k0);
        }
#pragma unroll
        for (int k = 0; k < BK; ++k) {
            float ar[8], br[4];
            *(float4*)(ar)     = *(const float4*)&As[buf][k][ty * 8];
            *(float4*)(ar + 4) = *(const float4*)&As[buf][k][ty * 8 + 4];
            *(float4*)(br)     = *(const float4*)&Bs[buf][k][tx * 4];
#pragma unroll
            for (int i = 0; i < 8; ++i)
#pragma unroll
                for (int j = 0; j < 4; ++j)
                    acc[i][j] = fmaf(ar[i], br[j], acc[i][j]);
        }
        if (t < NT - 1) {
            int nb2 = buf ^ 1;
            As[nb2][a_col + 0][a_row] = pa0.x; As[nb2][a_col + 1][a_row] = pa0.y;
            As[nb2][a_col + 2][a_row] = pa0.z; As[nb2][a_col + 3][a_row] = pa0.w;
            As[nb2][a_col + 4][a_row] = pa1.x; As[nb2][a_col + 5][a_row] = pa1.y;
            As[nb2][a_col + 6][a_row] = pa1.z; As[nb2][a_col + 7][a_row] = pa1.w;
            Bs[nb2][b_col + 0][b_row] = pb0.x; Bs[nb2][b_col + 1][b_row] = pb0.y;
            Bs[nb2][b_col + 2][b_row] = pb0.z; Bs[nb2][b_col + 3][b_row] = pb0.w;
        }
        __syncthreads();
        buf ^= 1;
    }

    // epilogue: p = proj^2, store; per-row partial sums via 16-lane xor reduce
#pragma unroll
    for (int i = 0; i < 8; ++i) {
        int m = mb + ty * 8 + i;
        float4 p;
        p.x = acc[i][0] * acc[i][0];
        p.y = acc[i][1] * acc[i][1];
        p.z = acc[i][2] * acc[i][2];
        p.w = acc[i][3] * acc[i][3];
        *(float4*)&P[(size_t)m * VV + nb + tx * 4] = p;
        float sum = p.x + p.y + p.z + p.w;
        sum += __shfl_xor_sync(0xffffffffu, sum, 1);
        sum += __shfl_xor_sync(0xffffffffu, sum, 2);
        sum += __shfl_xor_sync(0xffffffffu, sum, 4);
        sum += __shfl_xor_sync(0xffffffffu, sum, 8);
        if (tx == 0) atomicAdd(&g_rowsum[m], sum);
    }
}

// ---------------------------------------------------------------------------
// threefry2x32 (JAX-exact, key = (0, 42)) + gumbel
// ---------------------------------------------------------------------------
__device__ __forceinline__ unsigned rotl32(unsigned x, int r) {
    return (x << r) | (x >> (32 - r));
}

__device__ __forceinline__ void threefry2x32(unsigned k0, unsigned k1,
                                             unsigned& x0, unsigned& x1) {
    unsigned ks0 = k0, ks1 = k1, ks2 = k0 ^ k1 ^ 0x1BD11BDAu;
    x0 += ks0; x1 += ks1;
#define TF_R4(a, b, c, d)                                   \
    x0 += x1; x1 = rotl32(x1, a); x1 ^= x0;                 \
    x0 += x1; x1 = rotl32(x1, b); x1 ^= x0;                 \
    x0 += x1; x1 = rotl32(x1, c); x1 ^= x0;                 \
    x0 += x1; x1 = rotl32(x1, d); x1 ^= x0;
    TF_R4(13, 15, 26, 6)  x0 += ks1; x1 += ks2 + 1u;
    TF_R4(17, 29, 16, 24) x0 += ks2; x1 += ks0 + 2u;
    TF_R4(13, 15, 26, 6)  x0 += ks0; x1 += ks1 + 3u;
    TF_R4(17, 29, 16, 24) x0 += ks1; x1 += ks2 + 4u;
    TF_R4(13, 15, 26, 6)  x0 += ks2; x1 += ks0 + 5u;
#undef TF_R4
}

// gumbel noise for element (b, s*V+v); flat iota order (B,S,V), even split
__device__ __forceinline__ float gumbel_noise(int b, unsigned sv) {
    const unsigned half = (unsigned)SS * (unsigned)VV;  // 65,536,000 = total/2
    unsigned x0 = sv, x1 = sv + half;
    threefry2x32(0u, 42u, x0, x1);
    unsigned bits = (b == 0) ? x0 : x1;
    unsigned fb = (bits >> 9) | 0x3f800000u;
    float f = __uint_as_float(fb) - 1.0f;        // [0,1)
    const float tiny = 1.1754943508222875e-38f;  // FLT_MIN
    float u = f * (1.0f - tiny) + tiny;
    u = fmaxf(tiny, u);
    return -logf(-logf(u));
}

// ---------------------------------------------------------------------------
// finalize: normalize probs in place; tokens = -1 unless coherence > threshold,
// in which case do exact JAX gumbel-argmax over the row.
// ---------------------------------------------------------------------------
__global__ void __launch_bounds__(256) finalize_kernel(float* __restrict__ out) {
    int row = blockIdx.x;
    int b = row >> 11;
    int s = row & (SS - 1);
    int tid = threadIdx.x;
    float inv = 1.0f / (g_rowsum[row] + 1e-8f);
    float coh = g_coh[row];
    float* pr = out + NROWS + (size_t)row * VV;

    if (coh <= THRESHOLD) {
        float4* p4 = (float4*)pr;
        for (int i = tid; i < VV / 4; i += 256) {
            float4 v = p4[i];
            v.x *= inv; v.y *= inv; v.z *= inv; v.w *= inv;
            p4[i] = v;
        }
        if (tid == 0) out[row] = -1.0f;
    } else {
        float best = __int_as_float(0xff800000);  // -inf
        int bi = VV;
        for (int v = tid; v < VV; v += 256) {
            float pv = pr[v] * inv;
            pr[v] = pv;
            float lg = logf(pv + 1e-30f) + gumbel_noise(b, (unsigned)s * VV + v);
            if (lg > best || (lg == best && v < bi)) { best = lg; bi = v; }
        }
        __shared__ float sv[256];
        __shared__ int si[256];
        sv[tid] = best; si[tid] = bi;
        __syncthreads();
        for (int off = 128; off > 0; off >>= 1) {
            if (tid < off) {
                if (sv[tid + off] > sv[tid] ||
                    (sv[tid + off] == sv[tid] && si[tid + off] < si[tid])) {
                    sv[tid] = sv[tid + off];
                    si[tid] = si[tid + off];
                }
            }
            __syncthreads();
        }
        if (tid == 0) out[row] = (float)si[0];
    }
}

// ---------------------------------------------------------------------------
extern "C" void kernel_launch(void* const* d_in, const int* in_sizes, int n_in,
                              void* d_out, int out_size) {
    const float* field = (const float*)d_in[0];          // (2,2048,1024)
    const float* ops   = (const float*)d_in[1];          // (32000,1024)
    float* out = (float*)d_out;                          // [tokens(4096) | probs(131072000)]

    zero_kernel<<<(NROWS + 255) / 256, 256>>>();
    coherence_kernel<<<NROWS, 128>>>(field);
    dim3 grid(NROWS / BM, VV / BN);                      // (32, 500); M fastest for B-tile reuse
    gemm_p_kernel<<<grid, 256>>>(field, ops, out + NROWS);
    finalize_kernel<<<NROWS, 256>>>(out);
}

// round 3
// speedup vs baseline: 2.8097x; 2.8097x over previous
#include <cuda_runtime.h>
#include <cuda_bf16.h>
#include <cstdint>

// Problem shape (fixed): field (2,2048,1024) f32, measurement_ops (32000,1024) f32
// Output: tokens (4096) then probs (4096,32000), float32, concatenated.
#define BB 2
#define SS 2048
#define DD 1024
#define VV 32000
#define NROWS (BB * SS)            // 4096
#define THRESHOLD 0.91f

// ---- GEMM tiling ----
#define TM 128
#define TN 128
#define BKC 32                     // K elems per chunk
#define NCHK (DD / BKC)            // 32
#define GM (NROWS / TM)            // 32
#define GN (VV / TN)               // 250
#define STAGE_B 32768u             // A(16KB)+B(16KB) per stage
#define NSTAGE 3
#define DYN_SMEM (NSTAGE * STAGE_B)   // 98304

// ---- device scratch (no cudaMalloc allowed) ----
// Interleaved bf16 layout: per source row of 1024 f32 -> 2048 bf16:
//   [chunk c 0..31][ hi k=0..31 | lo k=0..31 ]   (one 128B block per chunk)
__device__ float g_rowsum[NROWS];
__device__ float g_coh[NROWS];
__device__ __nv_bfloat16 g_A[(size_t)NROWS * 2048];
__device__ __nv_bfloat16 g_B[(size_t)VV * 2048];

// ===========================================================================
// PTX helpers (all sm_80-portable)
// ===========================================================================
__device__ __forceinline__ uint32_t smem_u32(const void* p) {
    uint32_t a;
    asm("{ .reg .u64 t; cvta.to.shared.u64 t, %1; cvt.u32.u64 %0, t; }" : "=r"(a) : "l"(p));
    return a;
}
__device__ __forceinline__ void cpasync16(uint32_t s, const void* g) {
    asm volatile("cp.async.cg.shared.global [%0], [%1], 16;"
                 :: "r"(s), "l"(__cvta_generic_to_global(g)) : "memory");
}
__device__ __forceinline__ void cp_commit() {
    asm volatile("cp.async.commit_group;" ::: "memory");
}
template <int N>
__device__ __forceinline__ void cp_wait() {
    asm volatile("cp.async.wait_group %0;" :: "n"(N) : "memory");
}
__device__ __forceinline__ void ldsm4(uint32_t* r, uint32_t addr) {
    asm volatile("ldmatrix.sync.aligned.m8n8.x4.shared.b16 {%0,%1,%2,%3}, [%4];"
                 : "=r"(r[0]), "=r"(r[1]), "=r"(r[2]), "=r"(r[3]) : "r"(addr));
}
__device__ __forceinline__ void mma16816(float* c, const uint32_t* a, const uint32_t* b) {
    asm volatile(
        "mma.sync.aligned.m16n8k16.row.col.f32.bf16.bf16.f32 "
        "{%0,%1,%2,%3}, {%4,%5,%6,%7}, {%8,%9}, {%0,%1,%2,%3};"
        : "+f"(c[0]), "+f"(c[1]), "+f"(c[2]), "+f"(c[3])
        : "r"(a[0]), "r"(a[1]), "r"(a[2]), "r"(a[3]), "r"(b[0]), "r"(b[1]));
}

// ===========================================================================
// zero scratch (graph is replayed; must reset every launch)
// ===========================================================================
__global__ void zero_kernel() {
    int i = blockIdx.x * blockDim.x + threadIdx.x;
    if (i < NROWS) g_rowsum[i] = 0.0f;
}

// ===========================================================================
// split fp32 -> interleaved bf16 hi/lo
// ===========================================================================
__device__ __forceinline__ void split_pair(const float2 v, __nv_bfloat162& h2, __nv_bfloat162& l2) {
    __nv_bfloat16 hx = __float2bfloat16_rn(v.x);
    __nv_bfloat16 hy = __float2bfloat16_rn(v.y);
    h2 = __nv_bfloat162(hx, hy);
    l2 = __nv_bfloat162(__float2bfloat16_rn(v.x - __bfloat162float(hx)),
                        __float2bfloat16_rn(v.y - __bfloat162float(hy)));
}

__global__ void split_kernel(const float* __restrict__ A, const float* __restrict__ B) {
    const size_t pA = (size_t)NROWS * 512;     // pairs in A
    const size_t pB = (size_t)VV * 512;
    const size_t total = pA + pB;
    size_t stride = (size_t)gridDim.x * blockDim.x;
    for (size_t i = (size_t)blockIdx.x * blockDim.x + threadIdx.x; i < total; i += stride) {
        const float* src;
        __nv_bfloat16* dst;
        size_t p;
        if (i < pA) { src = A; dst = g_A; p = i; }
        else        { src = B; dst = g_B; p = i - pA; }
        size_t row = p >> 9;               // /512
        int kp = (int)(p & 511);           // pair index within row (k = 2*kp)
        float2 v = *(const float2*)(src + row * 1024 + kp * 2);
        __nv_bfloat162 h2, l2;
        split_pair(v, h2, l2);
        int chunk = kp >> 4;               // 16 pairs per 32-elem chunk
        int kk = (kp & 15) * 2;
        __nv_bfloat16* obase = dst + row * 2048 + chunk * 64;
        *(__nv_bfloat162*)(obase + kk) = h2;
        *(__nv_bfloat162*)(obase + 32 + kk) = l2;
    }
}

// ===========================================================================
// coherence: per (b,s), 5x5 windowed Gram -> lambda_max / trace
// ===========================================================================
__global__ void __launch_bounds__(128) coherence_kernel(const float* __restrict__ field) {
    int row = blockIdx.x;
    int b = row >> 11;
    int s = row & (SS - 1);
    int tid = threadIdx.x;
    const float* base = field + (size_t)b * SS * DD;

    int   idxc[5];
    float valm[5];
    float cnt = 0.0f;
#pragma unroll
    for (int w = 0; w < 5; ++w) {
        int t = s - 2 + w;
        bool v = (t >= 0) && (t < SS);
        valm[w] = v ? 1.0f : 0.0f;
        cnt += valm[w];
        idxc[w] = t < 0 ? 0 : (t > SS - 1 ? SS - 1 : t);
    }
    float rcnt = 1.0f / cnt;

    float g[15];
#pragma unroll
    for (int k = 0; k < 15; ++k) g[k] = 0.0f;

    for (int d = tid; d < DD; d += 128) {
        float f[5];
#pragma unroll
        for (int w = 0; w < 5; ++w) f[w] = base[(size_t)idxc[w] * DD + d];
        float mean = 0.0f;
#pragma unroll
        for (int w = 0; w < 5; ++w) mean += f[w] * valm[w];
        mean *= rcnt;
        float c[5];
#pragma unroll
        for (int w = 0; w < 5; ++w) c[w] = (f[w] - mean) * valm[w];
        int k = 0;
#pragma unroll
        for (int w = 0; w < 5; ++w)
#pragma unroll
            for (int v = w; v < 5; ++v) g[k++] += c[w] * c[v];
    }

#pragma unroll
    for (int k = 0; k < 15; ++k) {
#pragma unroll
        for (int off = 16; off > 0; off >>= 1)
            g[k] += __shfl_xor_sync(0xffffffffu, g[k], off);
    }
    __shared__ float sg[4][15];
    int wid = tid >> 5, ln = tid & 31;
    if (ln == 0) {
#pragma unroll
        for (int k = 0; k < 15; ++k) sg[wid][k] = g[k];
    }
    __syncthreads();

    if (tid == 0) {
        float G[5][5];
        int k = 0;
        for (int w = 0; w < 5; ++w)
            for (int v = w; v < 5; ++v) {
                float val = (sg[0][k] + sg[1][k] + sg[2][k] + sg[3][k]) * rcnt;
                G[w][v] = val;
                G[v][w] = val;
                ++k;
            }
        float tr = 0.0f;
        for (int i = 0; i < 5; ++i) tr += G[i][i];

        float vv[5] = {0.8147f, -0.9058f, 0.1270f, 0.9134f, -0.6324f};
        for (int it = 0; it < 60; ++it) {
            float nv[5];
            for (int i = 0; i < 5; ++i) {
                float a = 0.0f;
                for (int j = 0; j < 5; ++j) a += G[i][j] * vv[j];
                nv[i] = a;
            }
            float n2 = 0.0f;
            for (int i = 0; i < 5; ++i) n2 += nv[i] * nv[i];
            float inv = rsqrtf(n2 + 1e-30f);
            for (int i = 0; i < 5; ++i) vv[i] = nv[i] * inv;
        }
        float lam = 0.0f;
        for (int i = 0; i < 5; ++i) {
            float gi = 0.0f;
            for (int j = 0; j < 5; ++j) gi += G[i][j] * vv[j];
            lam += vv[i] * gi;
        }
        g_coh[row] = lam / (tr + 1e-8f);
    }
}

// ===========================================================================
// bf16x3 mma.sync GEMM: P[m,n] = (A[m,:].B[n,:])^2, row sums via atomics.
// CTA 128x128, BK=32, 8 warps (2x4), 3-stage cp.async pipeline.
// SMEM rows: 128B = [hi 64B | lo 64B], XOR-(row&7) swizzle on 16B groups.
// ===========================================================================
__global__ void __launch_bounds__(256, 1)
gemm_kernel(float* __restrict__ P) {
    extern __shared__ char dsm[];
    const uint32_t base = smem_u32(dsm);
    const int tid = threadIdx.x;
    const int wid = tid >> 5, lane = tid & 31;
    const int warp_m = wid >> 2, warp_n = wid & 3;   // 2 x 4
    const int mb = blockIdx.x * TM, nb = blockIdx.y * TN;

    // per-lane ldmatrix octet geometry (same for A and B except row split)
    const int oct = lane >> 3, j = lane & 7;
    const uint32_t a_row0 = (uint32_t)(((oct & 1) * 8 + j) * 128);
    const int a_gh = oct >> 1;
    const uint32_t b_row0 = (uint32_t)(((oct >> 1) * 8 + j) * 128);
    const int b_gh = oct & 1;

    // ---- stage loader ----
    auto load_stage = [&](int s, int c) {
        uint32_t sA = base + (uint32_t)s * STAGE_B;
        uint32_t sB = sA + 16384u;
        const __nv_bfloat16* gA = g_A + (size_t)mb * 2048 + c * 64;
        const __nv_bfloat16* gB = g_B + (size_t)nb * 2048 + c * 64;
#pragma unroll
        for (int i = 0; i < 4; ++i) {
            int idx = tid + i * 256;
            int r = idx >> 3, jj = idx & 7;
            uint32_t sw = (uint32_t)((jj ^ (r & 7)) << 4);
            cpasync16(sA + (uint32_t)r * 128 + sw, gA + (size_t)r * 2048 + jj * 8);
        }
#pragma unroll
        for (int i = 0; i < 4; ++i) {
            int idx = tid + i * 256;
            int r = idx >> 3, jj = idx & 7;
            uint32_t sw = (uint32_t)((jj ^ (r & 7)) << 4);
            cpasync16(sB + (uint32_t)r * 128 + sw, gB + (size_t)r * 2048 + jj * 8);
        }
    };

    float acc[4][4][4];
#pragma unroll
    for (int m = 0; m < 4; ++m)
#pragma unroll
        for (int n = 0; n < 4; ++n)
#pragma unroll
            for (int k = 0; k < 4; ++k) acc[m][n][k] = 0.0f;

    load_stage(0, 0); cp_commit();
    load_stage(1, 1); cp_commit();

#pragma unroll 1
    for (int c = 0; c < NCHK; ++c) {
        cp_wait<1>();
        __syncthreads();

        const uint32_t sA = base + (uint32_t)(c % 3) * STAGE_B + (uint32_t)(warp_m * 64) * 128;
        const uint32_t sB = base + (uint32_t)(c % 3) * STAGE_B + 16384u + (uint32_t)(warp_n * 32) * 128;

#pragma unroll
        for (int ks = 0; ks < 2; ++ks) {
            const int gb = ks << 1;                 // k-step -> group base (hi)
            uint32_t Ah[4][4], Al[4][4], Bh[2][4], Bl[2][4];
#pragma unroll
            for (int mt = 0; mt < 4; ++mt) {
                uint32_t rb = sA + (uint32_t)(mt * 2048) + a_row0;
                ldsm4(Ah[mt], rb + (uint32_t)((((gb + a_gh)) ^ j) << 4));
                ldsm4(Al[mt], rb + (uint32_t)(((4 + gb + a_gh) ^ j) << 4));
            }
#pragma unroll
            for (int nt2 = 0; nt2 < 2; ++nt2) {
                uint32_t rb = sB + (uint32_t)(nt2 * 2048) + b_row0;
                ldsm4(Bh[nt2], rb + (uint32_t)((((gb + b_gh)) ^ j) << 4));
                ldsm4(Bl[nt2], rb + (uint32_t)(((4 + gb + b_gh) ^ j) << 4));
            }
            // 3 passes: hh, hl, lh
#pragma unroll
            for (int mt = 0; mt < 4; ++mt)
#pragma unroll
                for (int nt = 0; nt < 4; ++nt)
                    mma16816(acc[mt][nt], Ah[mt], &Bh[nt >> 1][(nt & 1) * 2]);
#pragma unroll
            for (int mt = 0; mt < 4; ++mt)
#pragma unroll
                for (int nt = 0; nt < 4; ++nt)
                    mma16816(acc[mt][nt], Ah[mt], &Bl[nt >> 1][(nt & 1) * 2]);
#pragma unroll
            for (int mt = 0; mt < 4; ++mt)
#pragma unroll
                for (int nt = 0; nt < 4; ++nt)
                    mma16816(acc[mt][nt], Al[mt], &Bh[nt >> 1][(nt & 1) * 2]);
        }

        if (c + 2 < NCHK) load_stage((c + 2) % 3, c + 2);
        cp_commit();
    }

    // ---- epilogue: square -> SMEM stage -> coalesced store + rowsum ----
    __syncthreads();                       // pipeline fully drained
    float* stg = reinterpret_cast<float*>(dsm);
    const int PAD = 132;
    const int g = lane >> 2, tig = lane & 3;
#pragma unroll
    for (int mt = 0; mt < 4; ++mt) {
        int r0 = warp_m * 64 + mt * 16 + g;
        int cl = warp_n * 32;
#pragma unroll
        for (int nt = 0; nt < 4; ++nt) {
            int cc = cl + nt * 8 + tig * 2;
            float2 p0, p1;
            p0.x = acc[mt][nt][0] * acc[mt][nt][0];
            p0.y = acc[mt][nt][1] * acc[mt][nt][1];
            p1.x = acc[mt][nt][2] * acc[mt][nt][2];
            p1.y = acc[mt][nt][3] * acc[mt][nt][3];
            *(float2*)(stg + (size_t)r0 * PAD + cc) = p0;
            *(float2*)(stg + (size_t)(r0 + 8) * PAD + cc) = p1;
        }
    }
    __syncthreads();

    // warp-per-row: 32 float4 per row; rowsum via warp reduce
#pragma unroll 1
    for (int it = tid; it < TM * 32; it += 256) {
        int r = it >> 5, c4 = it & 31;
        float4 v = *(const float4*)(stg + (size_t)r * PAD + c4 * 4);
        *(float4*)(P + (size_t)(mb + r) * VV + nb + c4 * 4) = v;
        float sum = v.x + v.y + v.z + v.w;
        sum += __shfl_xor_sync(0xffffffffu, sum, 1);
        sum += __shfl_xor_sync(0xffffffffu, sum, 2);
        sum += __shfl_xor_sync(0xffffffffu, sum, 4);
        sum += __shfl_xor_sync(0xffffffffu, sum, 8);
        sum += __shfl_xor_sync(0xffffffffu, sum, 16);
        if (lane == 0) atomicAdd(&g_rowsum[mb + r], sum);
    }
}

// ===========================================================================
// threefry2x32 (JAX-exact, key = (0, 42)) + gumbel
// ===========================================================================
__device__ __forceinline__ unsigned rotl32(unsigned x, int r) {
    return (x << r) | (x >> (32 - r));
}
__device__ __forceinline__ void threefry2x32(unsigned k0, unsigned k1,
                                             unsigned& x0, unsigned& x1) {
    unsigned ks0 = k0, ks1 = k1, ks2 = k0 ^ k1 ^ 0x1BD11BDAu;
    x0 += ks0; x1 += ks1;
#define TF_R4(a, b, c, d)                                   \
    x0 += x1; x1 = rotl32(x1, a); x1 ^= x0;                 \
    x0 += x1; x1 = rotl32(x1, b); x1 ^= x0;                 \
    x0 += x1; x1 = rotl32(x1, c); x1 ^= x0;                 \
    x0 += x1; x1 = rotl32(x1, d); x1 ^= x0;
    TF_R4(13, 15, 26, 6)  x0 += ks1; x1 += ks2 + 1u;
    TF_R4(17, 29, 16, 24) x0 += ks2; x1 += ks0 + 2u;
    TF_R4(13, 15, 26, 6)  x0 += ks0; x1 += ks1 + 3u;
    TF_R4(17, 29, 16, 24) x0 += ks1; x1 += ks2 + 4u;
    TF_R4(13, 15, 26, 6)  x0 += ks2; x1 += ks0 + 5u;
#undef TF_R4
}
__device__ __forceinline__ float gumbel_noise(int b, unsigned sv) {
    const unsigned half = (unsigned)SS * (unsigned)VV;
    unsigned x0 = sv, x1 = sv + half;
    threefry2x32(0u, 42u, x0, x1);
    unsigned bits = (b == 0) ? x0 : x1;
    unsigned fb = (bits >> 9) | 0x3f800000u;
    float f = __uint_as_float(fb) - 1.0f;
    const float tiny = 1.1754943508222875e-38f;
    float u = f * (1.0f - tiny) + tiny;
    u = fmaxf(tiny, u);
    return -logf(-logf(u));
}

// ===========================================================================
// finalize: normalize probs in place; tokens per coherence threshold
// ===========================================================================
__global__ void __launch_bounds__(256) finalize_kernel(float* __restrict__ out) {
    int row = blockIdx.x;
    int b = row >> 11;
    int s = row & (SS - 1);
    int tid = threadIdx.x;
    float inv = 1.0f / (g_rowsum[row] + 1e-8f);
    float coh = g_coh[row];
    float* pr = out + NROWS + (size_t)row * VV;

    if (coh <= THRESHOLD) {
        float4* p4 = (float4*)pr;
        for (int i = tid; i < VV / 4; i += 256) {
            float4 v = p4[i];
            v.x *= inv; v.y *= inv; v.z *= inv; v.w *= inv;
            p4[i] = v;
        }
        if (tid == 0) out[row] = -1.0f;
    } else {
        float best = __int_as_float(0xff800000);
        int bi = VV;
        for (int v = tid; v < VV; v += 256) {
            float pv = pr[v] * inv;
            pr[v] = pv;
            float lg = logf(pv + 1e-30f) + gumbel_noise(b, (unsigned)s * VV + v);
            if (lg > best || (lg == best && v < bi)) { best = lg; bi = v; }
        }
        __shared__ float sv[256];
        __shared__ int si[256];
        sv[tid] = best; si[tid] = bi;
        __syncthreads();
        for (int off = 128; off > 0; off >>= 1) {
            if (tid < off) {
                if (sv[tid + off] > sv[tid] ||
                    (sv[tid + off] == sv[tid] && si[tid + off] < si[tid])) {
                    sv[tid] = sv[tid + off];
                    si[tid] = si[tid + off];
                }
            }
            __syncthreads();
        }
        if (tid == 0) out[row] = (float)si[0];
    }
}

// ===========================================================================
extern "C" void kernel_launch(void* const* d_in, const int* in_sizes, int n_in,
                              void* d_out, int out_size) {
    const float* field = (const float*)d_in[0];
    const float* ops   = (const float*)d_in[1];
    float* out = (float*)d_out;

    cudaFuncSetAttribute(gemm_kernel, cudaFuncAttributeMaxDynamicSharedMemorySize, DYN_SMEM);

    zero_kernel<<<(NROWS + 255) / 256, 256>>>();
    split_kernel<<<4096, 256>>>(field, ops);
    coherence_kernel<<<NROWS, 128>>>(field);
    dim3 grid(GM, GN);
    gemm_kernel<<<grid, 256, DYN_SMEM>>>(out + NROWS);
    finalize_kernel<<<NROWS, 256>>>(out);
}

// round 4
// speedup vs baseline: 3.9669x; 1.4118x over previous
#include <cuda_runtime.h>
#include <cuda_fp16.h>
#include <cuda_bf16.h>
#include <cstdint>

// Problem shape (fixed): field (2,2048,1024) f32, measurement_ops (32000,1024) f32
// Output: tokens (4096) then probs (4096,32000), float32, concatenated.
#define BB 2
#define SS 2048
#define DD 1024
#define VV 32000
#define NROWS (BB * SS)            // 4096
#define THRESHOLD 0.91f
#define BSCALE 32.0f               // ops pre-scale; probs are scale-invariant

// ---- GEMM tiling ----
#define TM 128
#define TN 128
#define BKC 32                     // K elems per chunk
#define NCHK (DD / BKC)            // 32
#define GM (NROWS / TM)            // 32
#define GN (VV / TN)               // 250
#define A_STAGE 8192u              // 128 rows x 64B (fp16 k-chunk)
#define B_STAGE 16384u             // 128 rows x 128B (hi|lo fp16)
#define STAGE_B (A_STAGE + B_STAGE)   // 24KB
#define NSTAGE 4
#define DYN_SMEM (NSTAGE * STAGE_B)   // 98304 -> 96KB

// ---- device scratch (no cudaMalloc allowed) ----
// g_A: fp16, plain [row][k]  (1024 per row)
// g_B: fp16, interleaved [row][chunk c][ hi k32 | lo k32 ]  (2048 per row)
__device__ float g_rowsum[NROWS];
__device__ float g_coh[NROWS];
__device__ __half g_A[(size_t)NROWS * 1024];
__device__ __half g_B[(size_t)VV * 2048];

// ===========================================================================
// PTX helpers (all sm_80-portable)
// ===========================================================================
__device__ __forceinline__ uint32_t smem_u32(const void* p) {
    uint32_t a;
    asm("{ .reg .u64 t; cvta.to.shared.u64 t, %1; cvt.u32.u64 %0, t; }" : "=r"(a) : "l"(p));
    return a;
}
__device__ __forceinline__ void cpasync16(uint32_t s, const void* g) {
    asm volatile("cp.async.cg.shared.global [%0], [%1], 16;"
                 :: "r"(s), "l"(__cvta_generic_to_global(g)) : "memory");
}
__device__ __forceinline__ void cp_commit() {
    asm volatile("cp.async.commit_group;" ::: "memory");
}
template <int N>
__device__ __forceinline__ void cp_wait() {
    asm volatile("cp.async.wait_group %0;" :: "n"(N) : "memory");
}
__device__ __forceinline__ void ldsm4(uint32_t* r, uint32_t addr) {
    asm volatile("ldmatrix.sync.aligned.m8n8.x4.shared.b16 {%0,%1,%2,%3}, [%4];"
                 : "=r"(r[0]), "=r"(r[1]), "=r"(r[2]), "=r"(r[3]) : "r"(addr));
}
__device__ __forceinline__ void mma16816(float* c, const uint32_t* a, const uint32_t* b) {
    asm volatile(
        "mma.sync.aligned.m16n8k16.row.col.f32.f16.f16.f32 "
        "{%0,%1,%2,%3}, {%4,%5,%6,%7}, {%8,%9}, {%0,%1,%2,%3};"
        : "+f"(c[0]), "+f"(c[1]), "+f"(c[2]), "+f"(c[3])
        : "r"(a[0]), "r"(a[1]), "r"(a[2]), "r"(a[3]), "r"(b[0]), "r"(b[1]));
}

// ===========================================================================
// zero scratch (graph is replayed; must reset every launch)
// ===========================================================================
__global__ void zero_kernel() {
    int i = blockIdx.x * blockDim.x + threadIdx.x;
    if (i < NROWS) g_rowsum[i] = 0.0f;
}

// ===========================================================================
// split: A -> fp16 plain; B -> x32, fp16 hi/lo interleaved per 32-chunk
// ===========================================================================
__global__ void split_kernel(const float* __restrict__ A, const float* __restrict__ B) {
    const size_t pA = (size_t)NROWS * 512;     // float2 pairs in A
    const size_t pB = (size_t)VV * 512;
    const size_t total = pA + pB;
    size_t stride = (size_t)gridDim.x * blockDim.x;
    for (size_t i = (size_t)blockIdx.x * blockDim.x + threadIdx.x; i < total; i += stride) {
        if (i < pA) {
            size_t row = i >> 9;
            int kp = (int)(i & 511);
            float2 v = *(const float2*)(A + row * 1024 + kp * 2);
            __half2 h2(__float2half_rn(v.x), __float2half_rn(v.y));
            *(__half2*)(g_A + row * 1024 + kp * 2) = h2;
        } else {
            size_t p = i - pA;
            size_t row = p >> 9;
            int kp = (int)(p & 511);
            float2 v = *(const float2*)(B + row * 1024 + kp * 2);
            v.x *= BSCALE; v.y *= BSCALE;
            __half hx = __float2half_rn(v.x);
            __half hy = __float2half_rn(v.y);
            __half2 h2(hx, hy);
            __half2 l2(__float2half_rn(v.x - __half2float(hx)),
                       __float2half_rn(v.y - __half2float(hy)));
            int chunk = kp >> 4;               // 16 pairs per 32-elem chunk
            int kk = (kp & 15) * 2;
            __half* obase = g_B + row * 2048 + chunk * 64;
            *(__half2*)(obase + kk) = h2;
            *(__half2*)(obase + 32 + kk) = l2;
        }
    }
}

// ===========================================================================
// coherence: per (b,s), 5x5 windowed Gram -> lambda_max / trace
// ===========================================================================
__global__ void __launch_bounds__(128) coherence_kernel(const float* __restrict__ field) {
    int row = blockIdx.x;
    int b = row >> 11;
    int s = row & (SS - 1);
    int tid = threadIdx.x;
    const float* base = field + (size_t)b * SS * DD;

    int   idxc[5];
    float valm[5];
    float cnt = 0.0f;
#pragma unroll
    for (int w = 0; w < 5; ++w) {
        int t = s - 2 + w;
        bool v = (t >= 0) && (t < SS);
        valm[w] = v ? 1.0f : 0.0f;
        cnt += valm[w];
        idxc[w] = t < 0 ? 0 : (t > SS - 1 ? SS - 1 : t);
    }
    float rcnt = 1.0f / cnt;

    float g[15];
#pragma unroll
    for (int k = 0; k < 15; ++k) g[k] = 0.0f;

    for (int d = tid; d < DD; d += 128) {
        float f[5];
#pragma unroll
        for (int w = 0; w < 5; ++w) f[w] = base[(size_t)idxc[w] * DD + d];
        float mean = 0.0f;
#pragma unroll
        for (int w = 0; w < 5; ++w) mean += f[w] * valm[w];
        mean *= rcnt;
        float c[5];
#pragma unroll
        for (int w = 0; w < 5; ++w) c[w] = (f[w] - mean) * valm[w];
        int k = 0;
#pragma unroll
        for (int w = 0; w < 5; ++w)
#pragma unroll
            for (int v = w; v < 5; ++v) g[k++] += c[w] * c[v];
    }

#pragma unroll
    for (int k = 0; k < 15; ++k) {
#pragma unroll
        for (int off = 16; off > 0; off >>= 1)
            g[k] += __shfl_xor_sync(0xffffffffu, g[k], off);
    }
    __shared__ float sg[4][15];
    int wid = tid >> 5, ln = tid & 31;
    if (ln == 0) {
#pragma unroll
        for (int k = 0; k < 15; ++k) sg[wid][k] = g[k];
    }
    __syncthreads();

    if (tid == 0) {
        float G[5][5];
        int k = 0;
        for (int w = 0; w < 5; ++w)
            for (int v = w; v < 5; ++v) {
                float val = (sg[0][k] + sg[1][k] + sg[2][k] + sg[3][k]) * rcnt;
                G[w][v] = val;
                G[v][w] = val;
                ++k;
            }
        float tr = 0.0f;
        for (int i = 0; i < 5; ++i) tr += G[i][i];

        float vv[5] = {0.8147f, -0.9058f, 0.1270f, 0.9134f, -0.6324f};
        for (int it = 0; it < 60; ++it) {
            float nv[5];
            for (int i = 0; i < 5; ++i) {
                float a = 0.0f;
                for (int j = 0; j < 5; ++j) a += G[i][j] * vv[j];
                nv[i] = a;
            }
            float n2 = 0.0f;
            for (int i = 0; i < 5; ++i) n2 += nv[i] * nv[i];
            float inv = rsqrtf(n2 + 1e-30f);
            for (int i = 0; i < 5; ++i) vv[i] = nv[i] * inv;
        }
        float lam = 0.0f;
        for (int i = 0; i < 5; ++i) {
            float gi = 0.0f;
            for (int j = 0; j < 5; ++j) gi += G[i][j] * vv[j];
            lam += vv[i] * gi;
        }
        g_coh[row] = lam / (tr + 1e-8f);
    }
}

// ===========================================================================
// fp16 2-pass mma.sync GEMM: P[m,n] = (A[m,:].B[n,:])^2, row sums via atomics.
// CTA 128x128, BK=32, 8 warps (2x4), 4-stage cp.async pipeline, 2 CTAs/SM.
// A smem: 2 m-rows packed per 128B row, 16B-group swizzle ^(smemrow&7).
// B smem: 128B rows = [hi 64B | lo 64B], same swizzle.
// ===========================================================================
__global__ void __launch_bounds__(256, 2)
gemm_kernel(float* __restrict__ P) {
    extern __shared__ char dsm[];
    const uint32_t base = smem_u32(dsm);
    const int tid = threadIdx.x;
    const int wid = tid >> 5, lane = tid & 31;
    const int warp_m = wid >> 2, warp_n = wid & 3;   // 2 x 4
    const int mb = blockIdx.x * TM, nb = blockIdx.y * TN;

    // ldmatrix octet geometry
    const int oct = lane >> 3, j = lane & 7;
    const int a_m = (oct & 1) * 8 + j;               // m-row within 16
    const int a_gh = oct >> 1;                       // k 16B-half within k16
    const uint32_t b_row0 = (uint32_t)(((oct >> 1) * 8 + j) * 128);
    const int b_gh = oct & 1;

    // ---- stage loader ----
    auto load_stage = [&](int s, int c) {
        uint32_t sA = base + (uint32_t)s * STAGE_B;
        uint32_t sB = sA + A_STAGE;
        const __half* gA = g_A + (size_t)mb * 1024 + c * 32;
        const __half* gB = g_B + (size_t)nb * 2048 + c * 64;
        // A: 128 rows x 4 x 16B = 512 transfers
#pragma unroll
        for (int i = 0; i < 2; ++i) {
            int idx = tid + i * 256;
            int r = idx >> 2, jj = idx & 3;
            int srow = r >> 1;
            uint32_t slot = (uint32_t)((((r & 1) * 4 + jj) ^ (srow & 7)) << 4);
            cpasync16(sA + (uint32_t)srow * 128 + slot, gA + (size_t)r * 1024 + jj * 8);
        }
        // B: 128 rows x 8 x 16B = 1024 transfers
#pragma unroll
        for (int i = 0; i < 4; ++i) {
            int idx = tid + i * 256;
            int r = idx >> 3, jj = idx & 7;
            uint32_t slot = (uint32_t)((jj ^ (r & 7)) << 4);
            cpasync16(sB + (uint32_t)r * 128 + slot, gB + (size_t)r * 2048 + jj * 8);
        }
    };

    float acc[4][4][4];
#pragma unroll
    for (int m = 0; m < 4; ++m)
#pragma unroll
        for (int n = 0; n < 4; ++n)
#pragma unroll
            for (int k = 0; k < 4; ++k) acc[m][n][k] = 0.0f;

    load_stage(0, 0); cp_commit();
    load_stage(1, 1); cp_commit();
    load_stage(2, 2); cp_commit();

#pragma unroll 1
    for (int c = 0; c < NCHK; ++c) {
        cp_wait<2>();
        __syncthreads();

        const uint32_t stg = base + (uint32_t)(c & 3) * STAGE_B;
        const uint32_t sB = stg + A_STAGE + (uint32_t)(warp_n * 32) * 128;

#pragma unroll
        for (int ks = 0; ks < 2; ++ks) {
            const int gb = ks << 1;
            uint32_t Ah[4][4], Bh[2][4], Bl[2][4];
#pragma unroll
            for (int mt = 0; mt < 4; ++mt) {
                int m = warp_m * 64 + mt * 16 + a_m;
                int srow = m >> 1;
                uint32_t slot = (uint32_t)((((m & 1) * 4 + (gb + a_gh)) ^ (srow & 7)) << 4);
                ldsm4(Ah[mt], stg + (uint32_t)srow * 128 + slot);
            }
#pragma unroll
            for (int nt2 = 0; nt2 < 2; ++nt2) {
                uint32_t rb = sB + (uint32_t)(nt2 * 2048) + b_row0;
                ldsm4(Bh[nt2], rb + (uint32_t)(((gb + b_gh)) ^ j) * 16u);
                ldsm4(Bl[nt2], rb + (uint32_t)((4 + gb + b_gh) ^ j) * 16u);
            }
#pragma unroll
            for (int mt = 0; mt < 4; ++mt)
#pragma unroll
                for (int nt = 0; nt < 4; ++nt)
                    mma16816(acc[mt][nt], Ah[mt], &Bh[nt >> 1][(nt & 1) * 2]);
#pragma unroll
            for (int mt = 0; mt < 4; ++mt)
#pragma unroll
                for (int nt = 0; nt < 4; ++nt)
                    mma16816(acc[mt][nt], Ah[mt], &Bl[nt >> 1][(nt & 1) * 2]);
        }

        __syncthreads();
        if (c + 3 < NCHK) load_stage((c + 3) & 3, c + 3);
        cp_commit();
    }

    // ---- epilogue: square -> SMEM stage -> coalesced store + rowsum ----
    cp_wait<0>();
    __syncthreads();
    float* stg = reinterpret_cast<float*>(dsm);
    const int PAD = 132;
    const int g = lane >> 2, tig = lane & 3;
#pragma unroll
    for (int mt = 0; mt < 4; ++mt) {
        int r0 = warp_m * 64 + mt * 16 + g;
        int cl = warp_n * 32;
#pragma unroll
        for (int nt = 0; nt < 4; ++nt) {
            int cc = cl + nt * 8 + tig * 2;
            float2 p0, p1;
            p0.x = acc[mt][nt][0] * acc[mt][nt][0];
            p0.y = acc[mt][nt][1] * acc[mt][nt][1];
            p1.x = acc[mt][nt][2] * acc[mt][nt][2];
            p1.y = acc[mt][nt][3] * acc[mt][nt][3];
            *(float2*)(stg + (size_t)r0 * PAD + cc) = p0;
            *(float2*)(stg + (size_t)(r0 + 8) * PAD + cc) = p1;
        }
    }
    __syncthreads();

#pragma unroll 1
    for (int it = tid; it < TM * 32; it += 256) {
        int r = it >> 5, c4 = it & 31;
        float4 v = *(const float4*)(stg + (size_t)r * PAD + c4 * 4);
        *(float4*)(P + (size_t)(mb + r) * VV + nb + c4 * 4) = v;
        float sum = v.x + v.y + v.z + v.w;
        sum += __shfl_xor_sync(0xffffffffu, sum, 1);
        sum += __shfl_xor_sync(0xffffffffu, sum, 2);
        sum += __shfl_xor_sync(0xffffffffu, sum, 4);
        sum += __shfl_xor_sync(0xffffffffu, sum, 8);
        sum += __shfl_xor_sync(0xffffffffu, sum, 16);
        if (lane == 0) atomicAdd(&g_rowsum[mb + r], sum);
    }
}

// ===========================================================================
// threefry2x32 (JAX-exact, key = (0, 42)) + gumbel
// ===========================================================================
__device__ __forceinline__ unsigned rotl32(unsigned x, int r) {
    return (x << r) | (x >> (32 - r));
}
__device__ __forceinline__ void threefry2x32(unsigned k0, unsigned k1,
                                             unsigned& x0, unsigned& x1) {
    unsigned ks0 = k0, ks1 = k1, ks2 = k0 ^ k1 ^ 0x1BD11BDAu;
    x0 += ks0; x1 += ks1;
#define TF_R4(a, b, c, d)                                   \
    x0 += x1; x1 = rotl32(x1, a); x1 ^= x0;                 \
    x0 += x1; x1 = rotl32(x1, b); x1 ^= x0;                 \
    x0 += x1; x1 = rotl32(x1, c); x1 ^= x0;                 \
    x0 += x1; x1 = rotl32(x1, d); x1 ^= x0;
    TF_R4(13, 15, 26, 6)  x0 += ks1; x1 += ks2 + 1u;
    TF_R4(17, 29, 16, 24) x0 += ks2; x1 += ks0 + 2u;
    TF_R4(13, 15, 26, 6)  x0 += ks0; x1 += ks1 + 3u;
    TF_R4(17, 29, 16, 24) x0 += ks1; x1 += ks2 + 4u;
    TF_R4(13, 15, 26, 6)  x0 += ks2; x1 += ks0 + 5u;
#undef TF_R4
}
__device__ __forceinline__ float gumbel_noise(int b, unsigned sv) {
    const unsigned half = (unsigned)SS * (unsigned)VV;
    unsigned x0 = sv, x1 = sv + half;
    threefry2x32(0u, 42u, x0, x1);
    unsigned bits = (b == 0) ? x0 : x1;
    unsigned fb = (bits >> 9) | 0x3f800000u;
    float f = __uint_as_float(fb) - 1.0f;
    const float tiny = 1.1754943508222875e-38f;
    float u = f * (1.0f - tiny) + tiny;
    u = fmaxf(tiny, u);
    return -logf(-logf(u));
}

// ===========================================================================
// finalize: normalize probs in place; tokens per coherence threshold
// ===========================================================================
__global__ void __launch_bounds__(256) finalize_kernel(float* __restrict__ out) {
    int row = blockIdx.x;
    int b = row >> 11;
    int s = row & (SS - 1);
    int tid = threadIdx.x;
    float inv = 1.0f / (g_rowsum[row] + 1e-8f);
    float coh = g_coh[row];
    float* pr = out + NROWS + (size_t)row * VV;

    if (coh <= THRESHOLD) {
        float4* p4 = (float4*)pr;
        for (int i = tid; i < VV / 4; i += 256) {
            float4 v = p4[i];
            v.x *= inv; v.y *= inv; v.z *= inv; v.w *= inv;
            p4[i] = v;
        }
        if (tid == 0) out[row] = -1.0f;
    } else {
        float best = __int_as_float(0xff800000);
        int bi = VV;
        for (int v = tid; v < VV; v += 256) {
            float pv = pr[v] * inv;
            pr[v] = pv;
            float lg = logf(pv + 1e-30f) + gumbel_noise(b, (unsigned)s * VV + v);
            if (lg > best || (lg == best && v < bi)) { best = lg; bi = v; }
        }
        __shared__ float sv[256];
        __shared__ int si[256];
        sv[tid] = best; si[tid] = bi;
        __syncthreads();
        for (int off = 128; off > 0; off >>= 1) {
            if (tid < off) {
                if (sv[tid + off] > sv[tid] ||
                    (sv[tid + off] == sv[tid] && si[tid + off] < si[tid])) {
                    sv[tid] = sv[tid + off];
                    si[tid] = si[tid + off];
                }
            }
            __syncthreads();
        }
        if (tid == 0) out[row] = (float)si[0];
    }
}

// ===========================================================================
extern "C" void kernel_launch(void* const* d_in, const int* in_sizes, int n_in,
                              void* d_out, int out_size) {
    const float* field = (const float*)d_in[0];
    const float* ops   = (const float*)d_in[1];
    float* out = (float*)d_out;

    cudaFuncSetAttribute(gemm_kernel, cudaFuncAttributeMaxDynamicSharedMemorySize, DYN_SMEM);

    zero_kernel<<<(NROWS + 255) / 256, 256>>>();
    split_kernel<<<4096, 256>>>(field, ops);
    coherence_kernel<<<NROWS, 128>>>(field);
    dim3 grid(GM, GN);
    gemm_kernel<<<grid, 256, DYN_SMEM>>>(out + NROWS);
    finalize_kernel<<<NROWS, 256>>>(out);
}

// round 5
// speedup vs baseline: 6.6174x; 1.6682x over previous
#include <cuda_runtime.h>
#include <cuda_fp16.h>
#include <cuda_bf16.h>
#include <cstdint>

// Problem shape (fixed): field (2,2048,1024) f32, measurement_ops (32000,1024) f32
// Output: tokens (4096) then probs (4096,32000), float32, concatenated.
#define BB 2
#define SS 2048
#define DD 1024
#define VV 32000
#define NROWS (BB * SS)            // 4096
#define THRESHOLD 0.91f
#define BSCALE 32.0f               // ops pre-scale; probs are scale-invariant

// ---- GEMM tiling ----
#define TM 128
#define TN 128
#define BKC 64                     // K elems per chunk (one 128B fp16 row)
#define NCHK (DD / BKC)            // 16
#define GM (NROWS / TM)            // 32
#define GN (VV / TN)               // 250
#define A_STAGE 16384u             // 128 rows x 128B
#define B_STAGE 16384u
#define STAGE_B (A_STAGE + B_STAGE)   // 32KB
#define NSTAGE 3
#define DYN_SMEM (NSTAGE * STAGE_B)   // 96KB -> 2 CTAs/SM = 192KB

// ---- device scratch (no cudaMalloc allowed) ----
__device__ float g_rowsum[NROWS];
__device__ float g_coh[NROWS];
__device__ __half g_A[(size_t)NROWS * 1024];
__device__ __half g_B[(size_t)VV * 1024];

// ===========================================================================
// PTX helpers (all sm_80-portable)
// ===========================================================================
__device__ __forceinline__ uint32_t smem_u32(const void* p) {
    uint32_t a;
    asm("{ .reg .u64 t; cvta.to.shared.u64 t, %1; cvt.u32.u64 %0, t; }" : "=r"(a) : "l"(p));
    return a;
}
__device__ __forceinline__ void cpasync16(uint32_t s, const void* g) {
    asm volatile("cp.async.cg.shared.global [%0], [%1], 16;"
                 :: "r"(s), "l"(__cvta_generic_to_global(g)) : "memory");
}
__device__ __forceinline__ void cp_commit() {
    asm volatile("cp.async.commit_group;" ::: "memory");
}
template <int N>
__device__ __forceinline__ void cp_wait() {
    asm volatile("cp.async.wait_group %0;" :: "n"(N) : "memory");
}
__device__ __forceinline__ void ldsm4(uint32_t* r, uint32_t addr) {
    asm volatile("ldmatrix.sync.aligned.m8n8.x4.shared.b16 {%0,%1,%2,%3}, [%4];"
                 : "=r"(r[0]), "=r"(r[1]), "=r"(r[2]), "=r"(r[3]) : "r"(addr));
}
__device__ __forceinline__ void mma16816(float* c, const uint32_t* a, const uint32_t* b) {
    asm volatile(
        "mma.sync.aligned.m16n8k16.row.col.f32.f16.f16.f32 "
        "{%0,%1,%2,%3}, {%4,%5,%6,%7}, {%8,%9}, {%0,%1,%2,%3};"
        : "+f"(c[0]), "+f"(c[1]), "+f"(c[2]), "+f"(c[3])
        : "r"(a[0]), "r"(a[1]), "r"(a[2]), "r"(a[3]), "r"(b[0]), "r"(b[1]));
}

// ===========================================================================
// zero scratch (graph is replayed; must reset every launch)
// ===========================================================================
__global__ void zero_kernel() {
    int i = blockIdx.x * blockDim.x + threadIdx.x;
    if (i < NROWS) g_rowsum[i] = 0.0f;
}

// ===========================================================================
// split: A -> fp16 plain; B -> x32 fp16 plain
// ===========================================================================
__global__ void split_kernel(const float* __restrict__ A, const float* __restrict__ B) {
    const size_t pA = (size_t)NROWS * 512;     // float2 pairs in A
    const size_t pB = (size_t)VV * 512;
    const size_t total = pA + pB;
    size_t stride = (size_t)gridDim.x * blockDim.x;
    for (size_t i = (size_t)blockIdx.x * blockDim.x + threadIdx.x; i < total; i += stride) {
        if (i < pA) {
            float2 v = *(const float2*)(A + i * 2);
            __half2 h2(__float2half_rn(v.x), __float2half_rn(v.y));
            *(__half2*)(g_A + i * 2) = h2;
        } else {
            size_t p = i - pA;
            float2 v = *(const float2*)(B + p * 2);
            __half2 h2(__float2half_rn(v.x * BSCALE), __float2half_rn(v.y * BSCALE));
            *(__half2*)(g_B + p * 2) = h2;
        }
    }
}

// ===========================================================================
// coherence: per (b,s), 5x5 windowed Gram -> lambda_max / trace
// ===========================================================================
__global__ void __launch_bounds__(128) coherence_kernel(const float* __restrict__ field) {
    int row = blockIdx.x;
    int b = row >> 11;
    int s = row & (SS - 1);
    int tid = threadIdx.x;
    const float* base = field + (size_t)b * SS * DD;

    int   idxc[5];
    float valm[5];
    float cnt = 0.0f;
#pragma unroll
    for (int w = 0; w < 5; ++w) {
        int t = s - 2 + w;
        bool v = (t >= 0) && (t < SS);
        valm[w] = v ? 1.0f : 0.0f;
        cnt += valm[w];
        idxc[w] = t < 0 ? 0 : (t > SS - 1 ? SS - 1 : t);
    }
    float rcnt = 1.0f / cnt;

    float g[15];
#pragma unroll
    for (int k = 0; k < 15; ++k) g[k] = 0.0f;

    for (int d = tid; d < DD; d += 128) {
        float f[5];
#pragma unroll
        for (int w = 0; w < 5; ++w) f[w] = base[(size_t)idxc[w] * DD + d];
        float mean = 0.0f;
#pragma unroll
        for (int w = 0; w < 5; ++w) mean += f[w] * valm[w];
        mean *= rcnt;
        float c[5];
#pragma unroll
        for (int w = 0; w < 5; ++w) c[w] = (f[w] - mean) * valm[w];
        int k = 0;
#pragma unroll
        for (int w = 0; w < 5; ++w)
#pragma unroll
            for (int v = w; v < 5; ++v) g[k++] += c[w] * c[v];
    }

#pragma unroll
    for (int k = 0; k < 15; ++k) {
#pragma unroll
        for (int off = 16; off > 0; off >>= 1)
            g[k] += __shfl_xor_sync(0xffffffffu, g[k], off);
    }
    __shared__ float sg[4][15];
    int wid = tid >> 5, ln = tid & 31;
    if (ln == 0) {
#pragma unroll
        for (int k = 0; k < 15; ++k) sg[wid][k] = g[k];
    }
    __syncthreads();

    if (tid == 0) {
        float G[5][5];
        int k = 0;
        for (int w = 0; w < 5; ++w)
            for (int v = w; v < 5; ++v) {
                float val = (sg[0][k] + sg[1][k] + sg[2][k] + sg[3][k]) * rcnt;
                G[w][v] = val;
                G[v][w] = val;
                ++k;
            }
        float tr = 0.0f;
        for (int i = 0; i < 5; ++i) tr += G[i][i];

        float vv[5] = {0.8147f, -0.9058f, 0.1270f, 0.9134f, -0.6324f};
        for (int it = 0; it < 60; ++it) {
            float nv[5];
            for (int i = 0; i < 5; ++i) {
                float a = 0.0f;
                for (int j = 0; j < 5; ++j) a += G[i][j] * vv[j];
                nv[i] = a;
            }
            float n2 = 0.0f;
            for (int i = 0; i < 5; ++i) n2 += nv[i] * nv[i];
            float inv = rsqrtf(n2 + 1e-30f);
            for (int i = 0; i < 5; ++i) vv[i] = nv[i] * inv;
        }
        float lam = 0.0f;
        for (int i = 0; i < 5; ++i) {
            float gi = 0.0f;
            for (int j = 0; j < 5; ++j) gi += G[i][j] * vv[j];
            lam += vv[i] * gi;
        }
        g_coh[row] = lam / (tr + 1e-8f);
    }
}

// ===========================================================================
// single-pass fp16 mma.sync GEMM: P[m,n] = (A[m,:].B[n,:])^2, rowsums atomic.
// CTA 128x128, BK=64, 8 warps (2x4), 3-stage cp.async pipeline, 2 CTAs/SM,
// ONE __syncthreads per chunk; loads for stage c+2 issued before compute.
// SMEM rows: 128B (64 fp16), 16B-group swizzle ^(row&7).
// ===========================================================================
__global__ void __launch_bounds__(256, 2)
gemm_kernel(float* __restrict__ P) {
    extern __shared__ char dsm[];
    const uint32_t base = smem_u32(dsm);
    const int tid = threadIdx.x;
    const int wid = tid >> 5, lane = tid & 31;
    const int warp_m = wid >> 2, warp_n = wid & 3;   // 2 x 4
    const int mb = blockIdx.x * TM, nb = blockIdx.y * TN;

    // ldmatrix octet geometry
    const int oct = lane >> 3, j = lane & 7;
    const int a_m = (oct & 1) * 8 + j;               // m-row within 16
    const int a_gh = oct >> 1;                       // k 16B-half within k16
    const int b_n = (oct >> 1) * 8 + j;              // n-row within 16
    const int b_gh = oct & 1;

    // ---- stage loader: 128 rows x 8 groups each for A and B ----
    auto load_stage = [&](int s, int c) {
        uint32_t sA = base + (uint32_t)s * STAGE_B;
        uint32_t sB = sA + A_STAGE;
        const __half* gA = g_A + (size_t)mb * 1024 + c * 64;
        const __half* gB = g_B + (size_t)nb * 1024 + c * 64;
#pragma unroll
        for (int i = 0; i < 4; ++i) {
            int idx = tid + i * 256;
            int r = idx >> 3, jj = idx & 7;
            uint32_t slot = (uint32_t)((jj ^ (r & 7)) << 4);
            cpasync16(sA + (uint32_t)r * 128 + slot, gA + (size_t)r * 1024 + jj * 8);
        }
#pragma unroll
        for (int i = 0; i < 4; ++i) {
            int idx = tid + i * 256;
            int r = idx >> 3, jj = idx & 7;
            uint32_t slot = (uint32_t)((jj ^ (r & 7)) << 4);
            cpasync16(sB + (uint32_t)r * 128 + slot, gB + (size_t)r * 1024 + jj * 8);
        }
    };

    float acc[4][4][4];
#pragma unroll
    for (int m = 0; m < 4; ++m)
#pragma unroll
        for (int n = 0; n < 4; ++n)
#pragma unroll
            for (int k = 0; k < 4; ++k) acc[m][n][k] = 0.0f;

    load_stage(0, 0); cp_commit();
    load_stage(1, 1); cp_commit();

#pragma unroll 1
    for (int c = 0; c < NCHK; ++c) {
        cp_wait<1>();
        __syncthreads();

        // issue next stage's loads first (target stage was fully consumed
        // by the end of iteration c-1; the sync above guarantees it)
        if (c + 2 < NCHK) load_stage((c + 2) % 3, c + 2);
        cp_commit();

        const uint32_t stg = base + (uint32_t)(c % 3) * STAGE_B;
        const uint32_t sBb = stg + A_STAGE;

#pragma unroll
        for (int ks = 0; ks < 4; ++ks) {
            uint32_t Ah[4][4], Bh[2][4];
#pragma unroll
            for (int mt = 0; mt < 4; ++mt) {
                int m = warp_m * 64 + mt * 16 + a_m;
                uint32_t slot = (uint32_t)(((2 * ks + a_gh) ^ (m & 7)) << 4);
                ldsm4(Ah[mt], stg + (uint32_t)m * 128 + slot);
            }
#pragma unroll
            for (int nt2 = 0; nt2 < 2; ++nt2) {
                int n = warp_n * 32 + nt2 * 16 + b_n;
                uint32_t slot = (uint32_t)(((2 * ks + b_gh) ^ (n & 7)) << 4);
                ldsm4(Bh[nt2], sBb + (uint32_t)n * 128 + slot);
            }
#pragma unroll
            for (int mt = 0; mt < 4; ++mt)
#pragma unroll
                for (int nt = 0; nt < 4; ++nt)
                    mma16816(acc[mt][nt], Ah[mt], &Bh[nt >> 1][(nt & 1) * 2]);
        }
    }

    // ---- epilogue: square -> SMEM stage -> coalesced store + rowsum ----
    cp_wait<0>();
    __syncthreads();
    float* stg = reinterpret_cast<float*>(dsm);
    const int PAD = 132;
    const int g = lane >> 2, tig = lane & 3;
#pragma unroll
    for (int mt = 0; mt < 4; ++mt) {
        int r0 = warp_m * 64 + mt * 16 + g;
        int cl = warp_n * 32;
#pragma unroll
        for (int nt = 0; nt < 4; ++nt) {
            int cc = cl + nt * 8 + tig * 2;
            float2 p0, p1;
            p0.x = acc[mt][nt][0] * acc[mt][nt][0];
            p0.y = acc[mt][nt][1] * acc[mt][nt][1];
            p1.x = acc[mt][nt][2] * acc[mt][nt][2];
            p1.y = acc[mt][nt][3] * acc[mt][nt][3];
            *(float2*)(stg + (size_t)r0 * PAD + cc) = p0;
            *(float2*)(stg + (size_t)(r0 + 8) * PAD + cc) = p1;
        }
    }
    __syncthreads();

#pragma unroll 1
    for (int it = tid; it < TM * 32; it += 256) {
        int r = it >> 5, c4 = it & 31;
        float4 v = *(const float4*)(stg + (size_t)r * PAD + c4 * 4);
        *(float4*)(P + (size_t)(mb + r) * VV + nb + c4 * 4) = v;
        float sum = v.x + v.y + v.z + v.w;
        sum += __shfl_xor_sync(0xffffffffu, sum, 1);
        sum += __shfl_xor_sync(0xffffffffu, sum, 2);
        sum += __shfl_xor_sync(0xffffffffu, sum, 4);
        sum += __shfl_xor_sync(0xffffffffu, sum, 8);
        sum += __shfl_xor_sync(0xffffffffu, sum, 16);
        if (lane == 0) atomicAdd(&g_rowsum[mb + r], sum);
    }
}

// ===========================================================================
// threefry2x32 (JAX-exact, key = (0, 42)) + gumbel
// ===========================================================================
__device__ __forceinline__ unsigned rotl32(unsigned x, int r) {
    return (x << r) | (x >> (32 - r));
}
__device__ __forceinline__ void threefry2x32(unsigned k0, unsigned k1,
                                             unsigned& x0, unsigned& x1) {
    unsigned ks0 = k0, ks1 = k1, ks2 = k0 ^ k1 ^ 0x1BD11BDAu;
    x0 += ks0; x1 += ks1;
#define TF_R4(a, b, c, d)                                   \
    x0 += x1; x1 = rotl32(x1, a); x1 ^= x0;                 \
    x0 += x1; x1 = rotl32(x1, b); x1 ^= x0;                 \
    x0 += x1; x1 = rotl32(x1, c); x1 ^= x0;                 \
    x0 += x1; x1 = rotl32(x1, d); x1 ^= x0;
    TF_R4(13, 15, 26, 6)  x0 += ks1; x1 += ks2 + 1u;
    TF_R4(17, 29, 16, 24) x0 += ks2; x1 += ks0 + 2u;
    TF_R4(13, 15, 26, 6)  x0 += ks0; x1 += ks1 + 3u;
    TF_R4(17, 29, 16, 24) x0 += ks1; x1 += ks2 + 4u;
    TF_R4(13, 15, 26, 6)  x0 += ks2; x1 += ks0 + 5u;
#undef TF_R4
}
__device__ __forceinline__ float gumbel_noise(int b, unsigned sv) {
    const unsigned half = (unsigned)SS * (unsigned)VV;
    unsigned x0 = sv, x1 = sv + half;
    threefry2x32(0u, 42u, x0, x1);
    unsigned bits = (b == 0) ? x0 : x1;
    unsigned fb = (bits >> 9) | 0x3f800000u;
    float f = __uint_as_float(fb) - 1.0f;
    const float tiny = 1.1754943508222875e-38f;
    float u = f * (1.0f - tiny) + tiny;
    u = fmaxf(tiny, u);
    return -logf(-logf(u));
}

// ===========================================================================
// finalize: normalize probs in place; tokens per coherence threshold
// ===========================================================================
__global__ void __launch_bounds__(256) finalize_kernel(float* __restrict__ out) {
    int row = blockIdx.x;
    int b = row >> 11;
    int s = row & (SS - 1);
    int tid = threadIdx.x;
    float inv = 1.0f / (g_rowsum[row] + 1e-8f);
    float coh = g_coh[row];
    float* pr = out + NROWS + (size_t)row * VV;

    if (coh <= THRESHOLD) {
        float4* p4 = (float4*)pr;
        for (int i = tid; i < VV / 4; i += 256) {
            float4 v = p4[i];
            v.x *= inv; v.y *= inv; v.z *= inv; v.w *= inv;
            p4[i] = v;
        }
        if (tid == 0) out[row] = -1.0f;
    } else {
        float best = __int_as_float(0xff800000);
        int bi = VV;
        for (int v = tid; v < VV; v += 256) {
            float pv = pr[v] * inv;
            pr[v] = pv;
            float lg = logf(pv + 1e-30f) + gumbel_noise(b, (unsigned)s * VV + v);
            if (lg > best || (lg == best && v < bi)) { best = lg; bi = v; }
        }
        __shared__ float sv[256];
        __shared__ int si[256];
        sv[tid] = best; si[tid] = bi;
        __syncthreads();
        for (int off = 128; off > 0; off >>= 1) {
            if (tid < off) {
                if (sv[tid + off] > sv[tid] ||
                    (sv[tid + off] == sv[tid] && si[tid + off] < si[tid])) {
                    sv[tid] = sv[tid + off];
                    si[tid] = si[tid + off];
                }
            }
            __syncthreads();
        }
        if (tid == 0) out[row] = (float)si[0];
    }
}

// ===========================================================================
extern "C" void kernel_launch(void* const* d_in, const int* in_sizes, int n_in,
                              void* d_out, int out_size) {
    const float* field = (const float*)d_in[0];
    const float* ops   = (const float*)d_in[1];
    float* out = (float*)d_out;

    cudaFuncSetAttribute(gemm_kernel, cudaFuncAttributeMaxDynamicSharedMemorySize, DYN_SMEM);

    zero_kernel<<<(NROWS + 255) / 256, 256>>>();
    split_kernel<<<4096, 256>>>(field, ops);
    coherence_kernel<<<NROWS, 128>>>(field);
    dim3 grid(GM, GN);
    gemm_kernel<<<grid, 256, DYN_SMEM>>>(out + NROWS);
    finalize_kernel<<<NROWS, 256>>>(out);
}